// round 2
// baseline (speedup 1.0000x reference)
#include <cuda_runtime.h>
#include <math_constants.h>

// Problem constants
constexpr int B_ = 2;
constexpr int N_ = 2048;
constexpr int C_ = 1024;
constexpr int H_ = 16;
constexpr int D_ = 64;
constexpr int M_ = B_ * N_;      // 4096 rows of x
constexpr float SCALE = 0.125f;  // D^-0.5

// Scratch (device globals; no allocation allowed)
__device__ float g_q[(size_t)B_ * H_ * N_ * D_];   // [B*H, N, D]
__device__ float g_k[(size_t)B_ * H_ * N_ * D_];
__device__ float g_v[(size_t)B_ * H_ * N_ * D_];
__device__ float g_ao[(size_t)B_ * N_ * C_];       // attention output, [B*N, C]

// ---------------------------------------------------------------------------
// Kernel 1: qkv = x @ qkv_w^T, fused RoPE epilogue, scatter to g_q/g_k/g_v
// GEMM: M=4096, Nout=3072, K=1024. Tiles 64x64x16, 256 thr, 4x4 microtile.
// ---------------------------------------------------------------------------
__global__ __launch_bounds__(256) void qkv_rope_kernel(
    const float* __restrict__ x, const float* __restrict__ w,
    const float* __restrict__ fcos, const float* __restrict__ fsin)
{
    __shared__ float As[16][64];
    __shared__ float Bs[16][64];

    const int tid = threadIdx.x;
    const int tx = tid & 15;
    const int ty = tid >> 4;
    const int m0 = blockIdx.y * 64;
    const int n0 = blockIdx.x * 64;
    const int lr = tid >> 2;          // 0..63
    const int lc = (tid & 3) * 4;     // 0,4,8,12

    float acc[4][4] = {};

    const float* xp = x + (size_t)(m0 + lr) * 1024 + lc;
    const float* wp = w + (size_t)(n0 + lr) * 1024 + lc;

    for (int k0 = 0; k0 < 1024; k0 += 16) {
        float4 av = *(const float4*)(xp + k0);
        float4 bv = *(const float4*)(wp + k0);
        As[lc + 0][lr] = av.x; As[lc + 1][lr] = av.y;
        As[lc + 2][lr] = av.z; As[lc + 3][lr] = av.w;
        Bs[lc + 0][lr] = bv.x; Bs[lc + 1][lr] = bv.y;
        Bs[lc + 2][lr] = bv.z; Bs[lc + 3][lr] = bv.w;
        __syncthreads();
#pragma unroll
        for (int kk = 0; kk < 16; kk++) {
            float4 a = *(const float4*)&As[kk][ty * 4];
            float4 b = *(const float4*)&Bs[kk][tx * 4];
            float ar[4] = {a.x, a.y, a.z, a.w};
            float br[4] = {b.x, b.y, b.z, b.w};
#pragma unroll
            for (int i = 0; i < 4; i++)
#pragma unroll
                for (int j = 0; j < 4; j++)
                    acc[i][j] = fmaf(ar[i], br[j], acc[i][j]);
        }
        __syncthreads();
    }

    // Epilogue: decode column -> (part, h, d); RoPE for q/k; scatter.
    const int col0 = n0 + tx * 4;            // aligned to 4
    const int part = col0 >> 10;             // 0=q, 1=k, 2=v
    const int h = (col0 >> 6) & (H_ - 1);
    const int dbase = col0 & (D_ - 1);       // multiple of 4

#pragma unroll
    for (int i = 0; i < 4; i++) {
        const int m = m0 + ty * 4 + i;
        const int b = m >> 11;               // / N_
        const int nr = m & (N_ - 1);
        const size_t dst_off = (((size_t)(b * H_ + h) * N_) + nr) * D_ + dbase;
        if (part == 2) {
            float4 o = {acc[i][0], acc[i][1], acc[i][2], acc[i][3]};
            *(float4*)&g_v[dst_off] = o;
        } else {
            float* dst = (part == 0) ? g_q : g_k;
            float4 o;
            {
                const int f0 = (dbase >> 1);
                const float c0 = fcos[nr * 32 + f0];
                const float s0 = fsin[nr * 32 + f0];
                o.x = acc[i][0] * c0 - acc[i][1] * s0;
                o.y = acc[i][0] * s0 + acc[i][1] * c0;
                const float c1 = fcos[nr * 32 + f0 + 1];
                const float s1 = fsin[nr * 32 + f0 + 1];
                o.z = acc[i][2] * c1 - acc[i][3] * s1;
                o.w = acc[i][2] * s1 + acc[i][3] * c1;
            }
            *(float4*)&dst[dst_off] = o;
        }
    }
}

// ---------------------------------------------------------------------------
// Kernel 2: flash attention. Block handles 64 queries of one (b,h).
// smem: Qt[d][q] (Q^T, pre-scaled), KtPs (K^T, reused for P), Vs[k][d].
// 3 * 64*64 * 4B = 49152 B = static shared limit (no cudaFuncSetAttribute).
// ---------------------------------------------------------------------------
__global__ __launch_bounds__(256) void attn_kernel()
{
    __shared__ float Qt[4096];     // Qt[d*64 + q], pre-scaled
    __shared__ float KtPs[4096];   // phase 1: Kt[d*64 + k]; phase 2: Ps[q*64 + k]
    __shared__ float Vs[4096];     // Vs[k*64 + d]

    const int tid = threadIdx.x;
    const int tx = tid & 15;
    const int ty = tid >> 4;
    const int bh = blockIdx.y;           // b*H + h
    const int q0 = blockIdx.x * 64;

    const float* qb = g_q + (size_t)bh * N_ * D_;
    const float* kb = g_k + (size_t)bh * N_ * D_;
    const float* vb = g_v + (size_t)bh * N_ * D_;

    const int lr = tid >> 2;             // 0..63
    const int lc = (tid & 3) * 4;

    // Load Q transposed + pre-scaled
#pragma unroll
    for (int ch = 0; ch < 4; ch++) {
        const int d = lc + ch * 16;
        float4 v = *(const float4*)(qb + (size_t)(q0 + lr) * D_ + d);
        Qt[(d + 0) * 64 + lr] = v.x * SCALE;
        Qt[(d + 1) * 64 + lr] = v.y * SCALE;
        Qt[(d + 2) * 64 + lr] = v.z * SCALE;
        Qt[(d + 3) * 64 + lr] = v.w * SCALE;
    }

    float m_i[4], l_i[4], acc[4][4];
#pragma unroll
    for (int i = 0; i < 4; i++) {
        m_i[i] = -CUDART_INF_F;
        l_i[i] = 0.f;
#pragma unroll
        for (int j = 0; j < 4; j++) acc[i][j] = 0.f;
    }

    for (int kt = 0; kt < N_; kt += 64) {
        __syncthreads();  // prev iter's P/V reads done before overwrite (also fences Qt stores)
#pragma unroll
        for (int ch = 0; ch < 4; ch++) {
            const int d = lc + ch * 16;
            float4 kv = *(const float4*)(kb + (size_t)(kt + lr) * D_ + d);
            KtPs[(d + 0) * 64 + lr] = kv.x;
            KtPs[(d + 1) * 64 + lr] = kv.y;
            KtPs[(d + 2) * 64 + lr] = kv.z;
            KtPs[(d + 3) * 64 + lr] = kv.w;
            float4 vv = *(const float4*)(vb + (size_t)(kt + lr) * D_ + d);
            *(float4*)&Vs[lr * 64 + d] = vv;
        }
        __syncthreads();

        // S = (Q*scale) @ K^T  (64x64x64)
        float s[4][4] = {};
#pragma unroll
        for (int kk = 0; kk < 64; kk++) {
            float4 a = *(const float4*)&Qt[kk * 64 + ty * 4];
            float4 b = *(const float4*)&KtPs[kk * 64 + tx * 4];
            float ar[4] = {a.x, a.y, a.z, a.w};
            float br[4] = {b.x, b.y, b.z, b.w};
#pragma unroll
            for (int i = 0; i < 4; i++)
#pragma unroll
                for (int j = 0; j < 4; j++)
                    s[i][j] = fmaf(ar[i], br[j], s[i][j]);
        }

        __syncthreads();  // all threads done reading Kt before P overwrites it

        // Online softmax (row stats replicated across the 16 tx-lanes)
        float alpha[4];
#pragma unroll
        for (int i = 0; i < 4; i++) {
            float mx = fmaxf(fmaxf(s[i][0], s[i][1]), fmaxf(s[i][2], s[i][3]));
#pragma unroll
            for (int off = 8; off >= 1; off >>= 1)
                mx = fmaxf(mx, __shfl_xor_sync(0xffffffffu, mx, off));
            const float mnew = fmaxf(m_i[i], mx);
            alpha[i] = __expf(m_i[i] - mnew);
            float rs = 0.f;
#pragma unroll
            for (int j = 0; j < 4; j++) {
                s[i][j] = __expf(s[i][j] - mnew);
                rs += s[i][j];
            }
#pragma unroll
            for (int off = 8; off >= 1; off >>= 1)
                rs += __shfl_xor_sync(0xffffffffu, rs, off);
            l_i[i] = l_i[i] * alpha[i] + rs;
            m_i[i] = mnew;
#pragma unroll
            for (int j = 0; j < 4; j++) acc[i][j] *= alpha[i];
        }

        // Write P into the (now free) Kt buffer, then O += P @ V
#pragma unroll
        for (int i = 0; i < 4; i++) {
            float4 p = {s[i][0], s[i][1], s[i][2], s[i][3]};
            *(float4*)&KtPs[(ty * 4 + i) * 64 + tx * 4] = p;
        }
        __syncthreads();

#pragma unroll
        for (int kk = 0; kk < 64; kk++) {
            float ar[4];
#pragma unroll
            for (int i = 0; i < 4; i++) ar[i] = KtPs[(ty * 4 + i) * 64 + kk];
            float4 b = *(const float4*)&Vs[kk * 64 + tx * 4];
            float br[4] = {b.x, b.y, b.z, b.w};
#pragma unroll
            for (int i = 0; i < 4; i++)
#pragma unroll
                for (int j = 0; j < 4; j++)
                    acc[i][j] = fmaf(ar[i], br[j], acc[i][j]);
        }
    }

    // Normalize and write to g_ao as [B*N, C]
    const int b = bh >> 4;
    const int h = bh & (H_ - 1);
#pragma unroll
    for (int i = 0; i < 4; i++) {
        const float inv = 1.0f / l_i[i];
        float4 o = {acc[i][0] * inv, acc[i][1] * inv,
                    acc[i][2] * inv, acc[i][3] * inv};
        const int q = q0 + ty * 4 + i;
        *(float4*)&g_ao[((size_t)(b * N_ + q)) * C_ + h * D_ + tx * 4] = o;
    }
}

// ---------------------------------------------------------------------------
// Kernel 3: out = g_ao @ proj_w^T + proj_b. M=4096, N=1024, K=1024.
// ---------------------------------------------------------------------------
__global__ __launch_bounds__(256) void proj_kernel(
    const float* __restrict__ w, const float* __restrict__ bias,
    float* __restrict__ out)
{
    __shared__ float As[16][64];
    __shared__ float Bs[16][64];

    const int tid = threadIdx.x;
    const int tx = tid & 15;
    const int ty = tid >> 4;
    const int m0 = blockIdx.y * 64;
    const int n0 = blockIdx.x * 64;
    const int lr = tid >> 2;
    const int lc = (tid & 3) * 4;

    float acc[4][4] = {};

    const float* xp = g_ao + (size_t)(m0 + lr) * 1024 + lc;
    const float* wp = w + (size_t)(n0 + lr) * 1024 + lc;

    for (int k0 = 0; k0 < 1024; k0 += 16) {
        float4 av = *(const float4*)(xp + k0);
        float4 bv = *(const float4*)(wp + k0);
        As[lc + 0][lr] = av.x; As[lc + 1][lr] = av.y;
        As[lc + 2][lr] = av.z; As[lc + 3][lr] = av.w;
        Bs[lc + 0][lr] = bv.x; Bs[lc + 1][lr] = bv.y;
        Bs[lc + 2][lr] = bv.z; Bs[lc + 3][lr] = bv.w;
        __syncthreads();
#pragma unroll
        for (int kk = 0; kk < 16; kk++) {
            float4 a = *(const float4*)&As[kk][ty * 4];
            float4 b = *(const float4*)&Bs[kk][tx * 4];
            float ar[4] = {a.x, a.y, a.z, a.w};
            float br[4] = {b.x, b.y, b.z, b.w};
#pragma unroll
            for (int i = 0; i < 4; i++)
#pragma unroll
                for (int j = 0; j < 4; j++)
                    acc[i][j] = fmaf(ar[i], br[j], acc[i][j]);
        }
        __syncthreads();
    }

    const int col0 = n0 + tx * 4;
    const float4 bb = *(const float4*)&bias[col0];
#pragma unroll
    for (int i = 0; i < 4; i++) {
        const int m = m0 + ty * 4 + i;
        float4 o = {acc[i][0] + bb.x, acc[i][1] + bb.y,
                    acc[i][2] + bb.z, acc[i][3] + bb.w};
        *(float4*)&out[(size_t)m * 1024 + col0] = o;
    }
}

// ---------------------------------------------------------------------------
extern "C" void kernel_launch(void* const* d_in, const int* in_sizes, int n_in,
                              void* d_out, int out_size)
{
    (void)in_sizes; (void)n_in; (void)out_size;
    const float* x      = (const float*)d_in[0];
    const float* qkv_w  = (const float*)d_in[1];
    const float* proj_w = (const float*)d_in[2];
    const float* proj_b = (const float*)d_in[3];
    const float* fcos   = (const float*)d_in[4];
    const float* fsin   = (const float*)d_in[5];
    float* out = (float*)d_out;

    // 1) QKV GEMM + RoPE
    qkv_rope_kernel<<<dim3(3 * C_ / 64, M_ / 64), 256>>>(x, qkv_w, fcos, fsin);
    // 2) Flash attention (static 48KB smem, no attribute call needed)
    attn_kernel<<<dim3(N_ / 64, B_ * H_), 256>>>();
    // 3) Output projection + bias
    proj_kernel<<<dim3(C_ / 64, M_ / 64), 256>>>(proj_w, proj_b, out);
}

// round 3
// speedup vs baseline: 1.5717x; 1.5717x over previous
#include <cuda_runtime.h>
#include <math_constants.h>

// Problem constants
constexpr int B_ = 2;
constexpr int N_ = 2048;
constexpr int C_ = 1024;
constexpr int H_ = 16;
constexpr int D_ = 64;
constexpr int M_ = B_ * N_;      // 4096 rows of x
constexpr float SCALE = 0.125f;  // D^-0.5

// Scratch (device globals; no allocation allowed)
__device__ float g_q[(size_t)B_ * H_ * N_ * D_];   // [B*H, N, D]
__device__ float g_k[(size_t)B_ * H_ * N_ * D_];
__device__ float g_v[(size_t)B_ * H_ * N_ * D_];
__device__ float g_ao[(size_t)B_ * N_ * C_];       // attention output, [B*N, C]

// ---------------------------------------------------------------------------
// tf32 helpers
// ---------------------------------------------------------------------------
__device__ __forceinline__ unsigned f2tf(float f) {
    unsigned u;
    asm("cvt.rna.tf32.f32 %0, %1;" : "=r"(u) : "f"(f));
    return u;
}

__device__ __forceinline__ void mma_tf32(
    float& c0, float& c1, float& c2, float& c3,
    unsigned a0, unsigned a1, unsigned a2, unsigned a3,
    unsigned b0, unsigned b1)
{
    asm volatile(
        "mma.sync.aligned.m16n8k8.row.col.f32.tf32.tf32.f32 "
        "{%0,%1,%2,%3}, {%4,%5,%6,%7}, {%8,%9}, {%0,%1,%2,%3};"
        : "+f"(c0), "+f"(c1), "+f"(c2), "+f"(c3)
        : "r"(a0), "r"(a1), "r"(a2), "r"(a3), "r"(b0), "r"(b1));
}

// ---------------------------------------------------------------------------
// Unified tf32 TN GEMM: C[M,Ncols] = A[M,K] @ W[Ncols,K]^T, K = 1024.
// Block 128x128x16, 8 warps (2x4), warp tile 64x32 (4 m16-tiles x 4 n8-tiles).
// Double-buffered smem, stride 20 (conflict-free fragment loads).
// EPI=0: qkv + RoPE scatter to g_q/g_k/g_v.  EPI=1: bias add -> out.
// ---------------------------------------------------------------------------
constexpr int SA = 20;  // smem row stride in elements (16 + 4 pad)

template<int EPI>
__global__ __launch_bounds__(256) void gemm_tf32_kernel(
    const float* __restrict__ Ain, const float* __restrict__ W,
    const float* __restrict__ fcos, const float* __restrict__ fsin,
    const float* __restrict__ bias, float* __restrict__ out)
{
    __shared__ unsigned As[2][128 * SA];
    __shared__ unsigned Bs[2][128 * SA];

    const float* A = (EPI == 1) ? g_ao : Ain;

    const int tid = threadIdx.x;
    const int w = tid >> 5;
    const int lane = tid & 31;
    const int g = lane >> 2;     // 0..7
    const int t = lane & 3;      // 0..3
    const int wm = w >> 2;       // 0..1
    const int wn = w & 3;        // 0..3

    const int m0 = blockIdx.y * 128;
    const int n0 = blockIdx.x * 128;

    // gmem load assignment: thread covers rows r0, r0+64; 4 floats at col c4
    const int r0 = tid >> 2;           // 0..63
    const int c4 = (tid & 3) * 4;      // 0,4,8,12

    const float* ap0 = A + (size_t)(m0 + r0) * 1024 + c4;
    const float* ap1 = ap0 + (size_t)64 * 1024;
    const float* bp0 = W + (size_t)(n0 + r0) * 1024 + c4;
    const float* bp1 = bp0 + (size_t)64 * 1024;

    float acc[4][4][4];
#pragma unroll
    for (int i = 0; i < 4; i++)
#pragma unroll
        for (int j = 0; j < 4; j++)
#pragma unroll
            for (int q = 0; q < 4; q++) acc[i][j][q] = 0.f;

    // prologue: load tile 0
    float4 va0 = *(const float4*)(ap0);
    float4 va1 = *(const float4*)(ap1);
    float4 vb0 = *(const float4*)(bp0);
    float4 vb1 = *(const float4*)(bp1);
    {
        uint4 u;
        u.x = f2tf(va0.x); u.y = f2tf(va0.y); u.z = f2tf(va0.z); u.w = f2tf(va0.w);
        *(uint4*)&As[0][r0 * SA + c4] = u;
        u.x = f2tf(va1.x); u.y = f2tf(va1.y); u.z = f2tf(va1.z); u.w = f2tf(va1.w);
        *(uint4*)&As[0][(r0 + 64) * SA + c4] = u;
        u.x = f2tf(vb0.x); u.y = f2tf(vb0.y); u.z = f2tf(vb0.z); u.w = f2tf(vb0.w);
        *(uint4*)&Bs[0][r0 * SA + c4] = u;
        u.x = f2tf(vb1.x); u.y = f2tf(vb1.y); u.z = f2tf(vb1.z); u.w = f2tf(vb1.w);
        *(uint4*)&Bs[0][(r0 + 64) * SA + c4] = u;
    }
    __syncthreads();

    for (int kt = 0; kt < 64; kt++) {
        const int buf = kt & 1;
        if (kt < 63) {
            const int k0 = (kt + 1) * 16;
            va0 = *(const float4*)(ap0 + k0);
            va1 = *(const float4*)(ap1 + k0);
            vb0 = *(const float4*)(bp0 + k0);
            vb1 = *(const float4*)(bp1 + k0);
        }

#pragma unroll
        for (int ks = 0; ks < 2; ks++) {
            unsigned afr[4][4];
#pragma unroll
            for (int i = 0; i < 4; i++) {
                const unsigned* p =
                    &As[buf][(wm * 64 + i * 16 + g) * SA + ks * 8 + t];
                afr[i][0] = p[0];
                afr[i][1] = p[8 * SA];
                afr[i][2] = p[4];
                afr[i][3] = p[8 * SA + 4];
            }
            unsigned bfr[4][2];
#pragma unroll
            for (int j = 0; j < 4; j++) {
                const unsigned* p =
                    &Bs[buf][(wn * 32 + j * 8 + g) * SA + ks * 8 + t];
                bfr[j][0] = p[0];
                bfr[j][1] = p[4];
            }
#pragma unroll
            for (int i = 0; i < 4; i++)
#pragma unroll
                for (int j = 0; j < 4; j++)
                    mma_tf32(acc[i][j][0], acc[i][j][1], acc[i][j][2], acc[i][j][3],
                             afr[i][0], afr[i][1], afr[i][2], afr[i][3],
                             bfr[j][0], bfr[j][1]);
        }

        if (kt < 63) {
            const int nb = buf ^ 1;
            uint4 u;
            u.x = f2tf(va0.x); u.y = f2tf(va0.y); u.z = f2tf(va0.z); u.w = f2tf(va0.w);
            *(uint4*)&As[nb][r0 * SA + c4] = u;
            u.x = f2tf(va1.x); u.y = f2tf(va1.y); u.z = f2tf(va1.z); u.w = f2tf(va1.w);
            *(uint4*)&As[nb][(r0 + 64) * SA + c4] = u;
            u.x = f2tf(vb0.x); u.y = f2tf(vb0.y); u.z = f2tf(vb0.z); u.w = f2tf(vb0.w);
            *(uint4*)&Bs[nb][r0 * SA + c4] = u;
            u.x = f2tf(vb1.x); u.y = f2tf(vb1.y); u.z = f2tf(vb1.z); u.w = f2tf(vb1.w);
            *(uint4*)&Bs[nb][(r0 + 64) * SA + c4] = u;
            __syncthreads();
        }
    }

    // ---------------- Epilogue ----------------
    // C fragment: thread holds cols (2t, 2t+1) of rows (g, g+8) per tile.
#pragma unroll
    for (int i = 0; i < 4; i++) {
        const int mlo = m0 + wm * 64 + i * 16 + g;
#pragma unroll
        for (int j = 0; j < 4; j++) {
            const int col = n0 + wn * 32 + j * 8 + 2 * t;  // even
            if (EPI == 1) {
                const float2 bb = *(const float2*)&bias[col];
                float2 o0 = {acc[i][j][0] + bb.x, acc[i][j][1] + bb.y};
                float2 o1 = {acc[i][j][2] + bb.x, acc[i][j][3] + bb.y};
                *(float2*)&out[(size_t)mlo * 1024 + col] = o0;
                *(float2*)&out[(size_t)(mlo + 8) * 1024 + col] = o1;
            } else {
                const int part = col >> 10;            // 0=q 1=k 2=v
                const int h = (col >> 6) & (H_ - 1);
                const int d = col & (D_ - 1);          // even
                const int f = d >> 1;
#pragma unroll
                for (int rr = 0; rr < 2; rr++) {
                    const int m = mlo + rr * 8;
                    const int b = m >> 11;
                    const int nr = m & (N_ - 1);
                    const float v0 = acc[i][j][rr * 2 + 0];
                    const float v1 = acc[i][j][rr * 2 + 1];
                    const size_t off =
                        (((size_t)(b * H_ + h) * N_) + nr) * D_ + d;
                    if (part == 2) {
                        float2 o = {v0, v1};
                        *(float2*)&g_v[off] = o;
                    } else {
                        const float c = fcos[nr * 32 + f];
                        const float s = fsin[nr * 32 + f];
                        float2 o = {v0 * c - v1 * s, v0 * s + v1 * c};
                        float* dst = (part == 0) ? g_q : g_k;
                        *(float2*)&dst[off] = o;
                    }
                }
            }
        }
    }
}

// ---------------------------------------------------------------------------
// Kernel 2: flash attention (SIMT fp32, unchanged from passing R2 version).
// ---------------------------------------------------------------------------
__global__ __launch_bounds__(256) void attn_kernel()
{
    __shared__ float Qt[4096];     // Qt[d*64 + q], pre-scaled
    __shared__ float KtPs[4096];   // phase 1: Kt[d*64 + k]; phase 2: Ps[q*64 + k]
    __shared__ float Vs[4096];     // Vs[k*64 + d]

    const int tid = threadIdx.x;
    const int tx = tid & 15;
    const int ty = tid >> 4;
    const int bh = blockIdx.y;           // b*H + h
    const int q0 = blockIdx.x * 64;

    const float* qb = g_q + (size_t)bh * N_ * D_;
    const float* kb = g_k + (size_t)bh * N_ * D_;
    const float* vb = g_v + (size_t)bh * N_ * D_;

    const int lr = tid >> 2;             // 0..63
    const int lc = (tid & 3) * 4;

#pragma unroll
    for (int ch = 0; ch < 4; ch++) {
        const int d = lc + ch * 16;
        float4 v = *(const float4*)(qb + (size_t)(q0 + lr) * D_ + d);
        Qt[(d + 0) * 64 + lr] = v.x * SCALE;
        Qt[(d + 1) * 64 + lr] = v.y * SCALE;
        Qt[(d + 2) * 64 + lr] = v.z * SCALE;
        Qt[(d + 3) * 64 + lr] = v.w * SCALE;
    }

    float m_i[4], l_i[4], acc[4][4];
#pragma unroll
    for (int i = 0; i < 4; i++) {
        m_i[i] = -CUDART_INF_F;
        l_i[i] = 0.f;
#pragma unroll
        for (int j = 0; j < 4; j++) acc[i][j] = 0.f;
    }

    for (int kt = 0; kt < N_; kt += 64) {
        __syncthreads();
#pragma unroll
        for (int ch = 0; ch < 4; ch++) {
            const int d = lc + ch * 16;
            float4 kv = *(const float4*)(kb + (size_t)(kt + lr) * D_ + d);
            KtPs[(d + 0) * 64 + lr] = kv.x;
            KtPs[(d + 1) * 64 + lr] = kv.y;
            KtPs[(d + 2) * 64 + lr] = kv.z;
            KtPs[(d + 3) * 64 + lr] = kv.w;
            float4 vv = *(const float4*)(vb + (size_t)(kt + lr) * D_ + d);
            *(float4*)&Vs[lr * 64 + d] = vv;
        }
        __syncthreads();

        float s[4][4] = {};
#pragma unroll
        for (int kk = 0; kk < 64; kk++) {
            float4 a = *(const float4*)&Qt[kk * 64 + ty * 4];
            float4 b = *(const float4*)&KtPs[kk * 64 + tx * 4];
            float ar[4] = {a.x, a.y, a.z, a.w};
            float br[4] = {b.x, b.y, b.z, b.w};
#pragma unroll
            for (int i = 0; i < 4; i++)
#pragma unroll
                for (int j = 0; j < 4; j++)
                    s[i][j] = fmaf(ar[i], br[j], s[i][j]);
        }

        __syncthreads();

        float alpha[4];
#pragma unroll
        for (int i = 0; i < 4; i++) {
            float mx = fmaxf(fmaxf(s[i][0], s[i][1]), fmaxf(s[i][2], s[i][3]));
#pragma unroll
            for (int off = 8; off >= 1; off >>= 1)
                mx = fmaxf(mx, __shfl_xor_sync(0xffffffffu, mx, off));
            const float mnew = fmaxf(m_i[i], mx);
            alpha[i] = __expf(m_i[i] - mnew);
            float rs = 0.f;
#pragma unroll
            for (int j = 0; j < 4; j++) {
                s[i][j] = __expf(s[i][j] - mnew);
                rs += s[i][j];
            }
#pragma unroll
            for (int off = 8; off >= 1; off >>= 1)
                rs += __shfl_xor_sync(0xffffffffu, rs, off);
            l_i[i] = l_i[i] * alpha[i] + rs;
            m_i[i] = mnew;
#pragma unroll
            for (int j = 0; j < 4; j++) acc[i][j] *= alpha[i];
        }

#pragma unroll
        for (int i = 0; i < 4; i++) {
            float4 p = {s[i][0], s[i][1], s[i][2], s[i][3]};
            *(float4*)&KtPs[(ty * 4 + i) * 64 + tx * 4] = p;
        }
        __syncthreads();

#pragma unroll
        for (int kk = 0; kk < 64; kk++) {
            float ar[4];
#pragma unroll
            for (int i = 0; i < 4; i++) ar[i] = KtPs[(ty * 4 + i) * 64 + kk];
            float4 b = *(const float4*)&Vs[kk * 64 + tx * 4];
            float br[4] = {b.x, b.y, b.z, b.w};
#pragma unroll
            for (int i = 0; i < 4; i++)
#pragma unroll
                for (int j = 0; j < 4; j++)
                    acc[i][j] = fmaf(ar[i], br[j], acc[i][j]);
        }
    }

    const int b = bh >> 4;
    const int h = bh & (H_ - 1);
#pragma unroll
    for (int i = 0; i < 4; i++) {
        const float inv = 1.0f / l_i[i];
        float4 o = {acc[i][0] * inv, acc[i][1] * inv,
                    acc[i][2] * inv, acc[i][3] * inv};
        const int q = q0 + ty * 4 + i;
        *(float4*)&g_ao[((size_t)(b * N_ + q)) * C_ + h * D_ + tx * 4] = o;
    }
}

// ---------------------------------------------------------------------------
extern "C" void kernel_launch(void* const* d_in, const int* in_sizes, int n_in,
                              void* d_out, int out_size)
{
    (void)in_sizes; (void)n_in; (void)out_size;
    const float* x      = (const float*)d_in[0];
    const float* qkv_w  = (const float*)d_in[1];
    const float* proj_w = (const float*)d_in[2];
    const float* proj_b = (const float*)d_in[3];
    const float* fcos   = (const float*)d_in[4];
    const float* fsin   = (const float*)d_in[5];
    float* out = (float*)d_out;

    // 1) QKV GEMM (tf32 tensor cores) + RoPE scatter
    gemm_tf32_kernel<0><<<dim3(3 * C_ / 128, M_ / 128), 256>>>(
        x, qkv_w, fcos, fsin, nullptr, nullptr);
    // 2) Flash attention (SIMT fp32)
    attn_kernel<<<dim3(N_ / 64, B_ * H_), 256>>>();
    // 3) Output projection (tf32 tensor cores) + bias
    gemm_tf32_kernel<1><<<dim3(C_ / 128, M_ / 128), 256>>>(
        nullptr, proj_w, nullptr, nullptr, proj_b, out);
}

// round 4
// speedup vs baseline: 3.0483x; 1.9394x over previous
#include <cuda_runtime.h>
#include <math_constants.h>

// Problem constants
constexpr int B_ = 2;
constexpr int N_ = 2048;
constexpr int C_ = 1024;
constexpr int H_ = 16;
constexpr int D_ = 64;
constexpr int M_ = B_ * N_;      // 4096 rows of x
constexpr float SCALE = 0.125f;  // D^-0.5

// Scratch (device globals; no allocation allowed)
__device__ float g_q[(size_t)B_ * H_ * N_ * D_];   // [B*H, N, D]
__device__ float g_k[(size_t)B_ * H_ * N_ * D_];
__device__ float g_v[(size_t)B_ * H_ * N_ * D_];
__device__ float g_ao[(size_t)B_ * N_ * C_];       // attention output, [B*N, C]

// ---------------------------------------------------------------------------
// tf32 helpers
// ---------------------------------------------------------------------------
__device__ __forceinline__ unsigned f2tf(float f) {
    unsigned u;
    asm("cvt.rna.tf32.f32 %0, %1;" : "=r"(u) : "f"(f));
    return u;
}

__device__ __forceinline__ void mma_tf32(
    float& c0, float& c1, float& c2, float& c3,
    unsigned a0, unsigned a1, unsigned a2, unsigned a3,
    unsigned b0, unsigned b1)
{
    asm volatile(
        "mma.sync.aligned.m16n8k8.row.col.f32.tf32.tf32.f32 "
        "{%0,%1,%2,%3}, {%4,%5,%6,%7}, {%8,%9}, {%0,%1,%2,%3};"
        : "+f"(c0), "+f"(c1), "+f"(c2), "+f"(c3)
        : "r"(a0), "r"(a1), "r"(a2), "r"(a3), "r"(b0), "r"(b1));
}

// ---------------------------------------------------------------------------
// Unified tf32 TN GEMM: C[M,Ncols] = A[M,K] @ W[Ncols,K]^T, K = 1024.
// Block 128x128x16, 8 warps (2x4), warp tile 64x32.
// EPI=0: qkv + RoPE scatter.  EPI=1: bias add -> out.
// ---------------------------------------------------------------------------
constexpr int SA = 20;  // smem row stride in elements (16 + 4 pad)

template<int EPI>
__global__ __launch_bounds__(256) void gemm_tf32_kernel(
    const float* __restrict__ Ain, const float* __restrict__ W,
    const float* __restrict__ fcos, const float* __restrict__ fsin,
    const float* __restrict__ bias, float* __restrict__ out)
{
    __shared__ unsigned As[2][128 * SA];
    __shared__ unsigned Bs[2][128 * SA];

    const float* A = (EPI == 1) ? g_ao : Ain;

    const int tid = threadIdx.x;
    const int w = tid >> 5;
    const int lane = tid & 31;
    const int g = lane >> 2;     // 0..7
    const int t = lane & 3;      // 0..3
    const int wm = w >> 2;       // 0..1
    const int wn = w & 3;        // 0..3

    const int m0 = blockIdx.y * 128;
    const int n0 = blockIdx.x * 128;

    const int r0 = tid >> 2;           // 0..63
    const int c4 = (tid & 3) * 4;      // 0,4,8,12

    const float* ap0 = A + (size_t)(m0 + r0) * 1024 + c4;
    const float* ap1 = ap0 + (size_t)64 * 1024;
    const float* bp0 = W + (size_t)(n0 + r0) * 1024 + c4;
    const float* bp1 = bp0 + (size_t)64 * 1024;

    float acc[4][4][4];
#pragma unroll
    for (int i = 0; i < 4; i++)
#pragma unroll
        for (int j = 0; j < 4; j++)
#pragma unroll
            for (int q = 0; q < 4; q++) acc[i][j][q] = 0.f;

    float4 va0 = *(const float4*)(ap0);
    float4 va1 = *(const float4*)(ap1);
    float4 vb0 = *(const float4*)(bp0);
    float4 vb1 = *(const float4*)(bp1);
    {
        uint4 u;
        u.x = f2tf(va0.x); u.y = f2tf(va0.y); u.z = f2tf(va0.z); u.w = f2tf(va0.w);
        *(uint4*)&As[0][r0 * SA + c4] = u;
        u.x = f2tf(va1.x); u.y = f2tf(va1.y); u.z = f2tf(va1.z); u.w = f2tf(va1.w);
        *(uint4*)&As[0][(r0 + 64) * SA + c4] = u;
        u.x = f2tf(vb0.x); u.y = f2tf(vb0.y); u.z = f2tf(vb0.z); u.w = f2tf(vb0.w);
        *(uint4*)&Bs[0][r0 * SA + c4] = u;
        u.x = f2tf(vb1.x); u.y = f2tf(vb1.y); u.z = f2tf(vb1.z); u.w = f2tf(vb1.w);
        *(uint4*)&Bs[0][(r0 + 64) * SA + c4] = u;
    }
    __syncthreads();

    for (int kt = 0; kt < 64; kt++) {
        const int buf = kt & 1;
        if (kt < 63) {
            const int k0 = (kt + 1) * 16;
            va0 = *(const float4*)(ap0 + k0);
            va1 = *(const float4*)(ap1 + k0);
            vb0 = *(const float4*)(bp0 + k0);
            vb1 = *(const float4*)(bp1 + k0);
        }

#pragma unroll
        for (int ks = 0; ks < 2; ks++) {
            unsigned afr[4][4];
#pragma unroll
            for (int i = 0; i < 4; i++) {
                const unsigned* p =
                    &As[buf][(wm * 64 + i * 16 + g) * SA + ks * 8 + t];
                afr[i][0] = p[0];
                afr[i][1] = p[8 * SA];
                afr[i][2] = p[4];
                afr[i][3] = p[8 * SA + 4];
            }
            unsigned bfr[4][2];
#pragma unroll
            for (int j = 0; j < 4; j++) {
                const unsigned* p =
                    &Bs[buf][(wn * 32 + j * 8 + g) * SA + ks * 8 + t];
                bfr[j][0] = p[0];
                bfr[j][1] = p[4];
            }
#pragma unroll
            for (int i = 0; i < 4; i++)
#pragma unroll
                for (int j = 0; j < 4; j++)
                    mma_tf32(acc[i][j][0], acc[i][j][1], acc[i][j][2], acc[i][j][3],
                             afr[i][0], afr[i][1], afr[i][2], afr[i][3],
                             bfr[j][0], bfr[j][1]);
        }

        if (kt < 63) {
            const int nb = buf ^ 1;
            uint4 u;
            u.x = f2tf(va0.x); u.y = f2tf(va0.y); u.z = f2tf(va0.z); u.w = f2tf(va0.w);
            *(uint4*)&As[nb][r0 * SA + c4] = u;
            u.x = f2tf(va1.x); u.y = f2tf(va1.y); u.z = f2tf(va1.z); u.w = f2tf(va1.w);
            *(uint4*)&As[nb][(r0 + 64) * SA + c4] = u;
            u.x = f2tf(vb0.x); u.y = f2tf(vb0.y); u.z = f2tf(vb0.z); u.w = f2tf(vb0.w);
            *(uint4*)&Bs[nb][r0 * SA + c4] = u;
            u.x = f2tf(vb1.x); u.y = f2tf(vb1.y); u.z = f2tf(vb1.z); u.w = f2tf(vb1.w);
            *(uint4*)&Bs[nb][(r0 + 64) * SA + c4] = u;
            __syncthreads();
        }
    }

    // Epilogue: thread holds cols (2t,2t+1) of rows (g, g+8) per tile.
#pragma unroll
    for (int i = 0; i < 4; i++) {
        const int mlo = m0 + wm * 64 + i * 16 + g;
#pragma unroll
        for (int j = 0; j < 4; j++) {
            const int col = n0 + wn * 32 + j * 8 + 2 * t;  // even
            if (EPI == 1) {
                const float2 bb = *(const float2*)&bias[col];
                float2 o0 = {acc[i][j][0] + bb.x, acc[i][j][1] + bb.y};
                float2 o1 = {acc[i][j][2] + bb.x, acc[i][j][3] + bb.y};
                *(float2*)&out[(size_t)mlo * 1024 + col] = o0;
                *(float2*)&out[(size_t)(mlo + 8) * 1024 + col] = o1;
            } else {
                const int part = col >> 10;            // 0=q 1=k 2=v
                const int h = (col >> 6) & (H_ - 1);
                const int d = col & (D_ - 1);          // even
                const int f = d >> 1;
#pragma unroll
                for (int rr = 0; rr < 2; rr++) {
                    const int m = mlo + rr * 8;
                    const int b = m >> 11;
                    const int nr = m & (N_ - 1);
                    const float v0 = acc[i][j][rr * 2 + 0];
                    const float v1 = acc[i][j][rr * 2 + 1];
                    const size_t off =
                        (((size_t)(b * H_ + h) * N_) + nr) * D_ + d;
                    if (part == 2) {
                        float2 o = {v0, v1};
                        *(float2*)&g_v[off] = o;
                    } else {
                        const float c = fcos[nr * 32 + f];
                        const float s = fsin[nr * 32 + f];
                        float2 o = {v0 * c - v1 * s, v0 * s + v1 * c};
                        float* dst = (part == 0) ? g_q : g_k;
                        *(float2*)&dst[off] = o;
                    }
                }
            }
        }
    }
}

// ---------------------------------------------------------------------------
// Kernel 2: tf32 tensor-core flash attention.
// Block: 128 queries x one (b,h). 8 warps, warp = m16 slab x full 64-key tile.
// Q fragments register-resident; K and V^T staged in smem (tf32, stride 68 =
// conflict-free B-frag LDS). P converted C-frag -> A-frag in-register (shfl).
// ---------------------------------------------------------------------------
constexpr int SK = 68;  // smem stride (64 + 4): bank = (4g + t + 8s) % 32, clean

__global__ __launch_bounds__(256) void attn_tc_kernel()
{
    __shared__ unsigned Ks[64 * SK];  // K[key][d], tf32
    __shared__ unsigned Vt[64 * SK];  // V^T[d][key], tf32

    const int tid = threadIdx.x;
    const int w = tid >> 5;
    const int lane = tid & 31;
    const int g = lane >> 2;
    const int t = lane & 3;

    const int bh = blockIdx.y;
    const int q0 = blockIdx.x * 128;
    const int qlo = q0 + w * 16 + g;      // row g of this warp's m16 slab

    const float* qb = g_q + (size_t)bh * N_ * D_;
    const float* kb = g_k + (size_t)bh * N_ * D_;
    const float* vb = g_v + (size_t)bh * N_ * D_;

    // Q A-fragments, pre-scaled, register-resident for the whole kernel.
    unsigned qf[8][4];
#pragma unroll
    for (int s = 0; s < 8; s++) {
        const float* plo = qb + (size_t)qlo * D_ + s * 8 + t;
        const float* phi = plo + 8 * D_;
        qf[s][0] = f2tf(plo[0] * SCALE);
        qf[s][1] = f2tf(phi[0] * SCALE);
        qf[s][2] = f2tf(plo[4] * SCALE);
        qf[s][3] = f2tf(phi[4] * SCALE);
    }

    float oacc[8][4];
#pragma unroll
    for (int j = 0; j < 8; j++)
#pragma unroll
        for (int q = 0; q < 4; q++) oacc[j][q] = 0.f;
    float m_lo = -CUDART_INF_F, m_hi = -CUDART_INF_F;
    float l_lo = 0.f, l_hi = 0.f;

    const int r0 = tid >> 2;           // 0..63
    const int c4 = (tid & 3) * 4;      // 0,4,8,12
    const int src_lo = (lane & 28) | (t >> 1);
    const int src_hi = src_lo + 2;
    const bool odd = t & 1;

    for (int kt = 0; kt < N_; kt += 64) {
        __syncthreads();  // prior tile's LDS reads done before overwrite
#pragma unroll
        for (int ch = 0; ch < 4; ch++) {
            const int c = c4 + ch * 16;
            float4 kv = *(const float4*)(kb + (size_t)(kt + r0) * D_ + c);
            uint4 u;
            u.x = f2tf(kv.x); u.y = f2tf(kv.y);
            u.z = f2tf(kv.z); u.w = f2tf(kv.w);
            *(uint4*)&Ks[r0 * SK + c] = u;
            float4 vv = *(const float4*)(vb + (size_t)(kt + r0) * D_ + c);
            Vt[(c + 0) * SK + r0] = f2tf(vv.x);
            Vt[(c + 1) * SK + r0] = f2tf(vv.y);
            Vt[(c + 2) * SK + r0] = f2tf(vv.z);
            Vt[(c + 3) * SK + r0] = f2tf(vv.w);
        }
        __syncthreads();

        // S = Q @ K^T : m16 x n64(keys) x k64(d)
        float sacc[8][4];
#pragma unroll
        for (int j = 0; j < 8; j++)
#pragma unroll
            for (int q = 0; q < 4; q++) sacc[j][q] = 0.f;
#pragma unroll
        for (int s = 0; s < 8; s++) {
#pragma unroll
            for (int j = 0; j < 8; j++) {
                const unsigned* p = &Ks[(j * 8 + g) * SK + s * 8 + t];
                mma_tf32(sacc[j][0], sacc[j][1], sacc[j][2], sacc[j][3],
                         qf[s][0], qf[s][1], qf[s][2], qf[s][3],
                         p[0], p[4]);
            }
        }

        // Online softmax. Rows: g -> elems {0,1}; g+8 -> elems {2,3}.
        float mx_lo = -CUDART_INF_F, mx_hi = -CUDART_INF_F;
#pragma unroll
        for (int j = 0; j < 8; j++) {
            mx_lo = fmaxf(mx_lo, fmaxf(sacc[j][0], sacc[j][1]));
            mx_hi = fmaxf(mx_hi, fmaxf(sacc[j][2], sacc[j][3]));
        }
#pragma unroll
        for (int off = 2; off >= 1; off >>= 1) {
            mx_lo = fmaxf(mx_lo, __shfl_xor_sync(0xffffffffu, mx_lo, off));
            mx_hi = fmaxf(mx_hi, __shfl_xor_sync(0xffffffffu, mx_hi, off));
        }
        const float mn_lo = fmaxf(m_lo, mx_lo);
        const float mn_hi = fmaxf(m_hi, mx_hi);
        const float al_lo = __expf(m_lo - mn_lo);
        const float al_hi = __expf(m_hi - mn_hi);
        float rs_lo = 0.f, rs_hi = 0.f;
#pragma unroll
        for (int j = 0; j < 8; j++) {
            sacc[j][0] = __expf(sacc[j][0] - mn_lo);
            sacc[j][1] = __expf(sacc[j][1] - mn_lo);
            sacc[j][2] = __expf(sacc[j][2] - mn_hi);
            sacc[j][3] = __expf(sacc[j][3] - mn_hi);
            rs_lo += sacc[j][0] + sacc[j][1];
            rs_hi += sacc[j][2] + sacc[j][3];
        }
#pragma unroll
        for (int off = 2; off >= 1; off >>= 1) {
            rs_lo += __shfl_xor_sync(0xffffffffu, rs_lo, off);
            rs_hi += __shfl_xor_sync(0xffffffffu, rs_hi, off);
        }
        l_lo = l_lo * al_lo + rs_lo;  m_lo = mn_lo;
        l_hi = l_hi * al_hi + rs_hi;  m_hi = mn_hi;
#pragma unroll
        for (int j = 0; j < 8; j++) {
            oacc[j][0] *= al_lo; oacc[j][1] *= al_lo;
            oacc[j][2] *= al_hi; oacc[j][3] *= al_hi;
        }

        // O += P @ V : per k-step s, build P A-frag from C-frag via quad shfl.
#pragma unroll
        for (int s = 0; s < 8; s++) {
            const float x0 = __shfl_sync(0xffffffffu, sacc[s][0], src_lo);
            const float x1 = __shfl_sync(0xffffffffu, sacc[s][1], src_lo);
            const float x2 = __shfl_sync(0xffffffffu, sacc[s][2], src_lo);
            const float x3 = __shfl_sync(0xffffffffu, sacc[s][3], src_lo);
            const float y0 = __shfl_sync(0xffffffffu, sacc[s][0], src_hi);
            const float y1 = __shfl_sync(0xffffffffu, sacc[s][1], src_hi);
            const float y2 = __shfl_sync(0xffffffffu, sacc[s][2], src_hi);
            const float y3 = __shfl_sync(0xffffffffu, sacc[s][3], src_hi);
            const unsigned a0 = f2tf(odd ? x1 : x0);
            const unsigned a1 = f2tf(odd ? x3 : x2);
            const unsigned a2 = f2tf(odd ? y1 : y0);
            const unsigned a3 = f2tf(odd ? y3 : y2);
#pragma unroll
            for (int jd = 0; jd < 8; jd++) {
                const unsigned* p = &Vt[(jd * 8 + g) * SK + s * 8 + t];
                mma_tf32(oacc[jd][0], oacc[jd][1], oacc[jd][2], oacc[jd][3],
                         a0, a1, a2, a3, p[0], p[4]);
            }
        }
    }

    // Normalize and write to g_ao [B*N, C]
    const float inv_lo = 1.0f / l_lo;
    const float inv_hi = 1.0f / l_hi;
    const int b = bh >> 4;
    const int h = bh & (H_ - 1);
#pragma unroll
    for (int jd = 0; jd < 8; jd++) {
        const int col = h * D_ + jd * 8 + 2 * t;
        float2 o0 = {oacc[jd][0] * inv_lo, oacc[jd][1] * inv_lo};
        float2 o1 = {oacc[jd][2] * inv_hi, oacc[jd][3] * inv_hi};
        *(float2*)&g_ao[((size_t)(b * N_ + qlo)) * C_ + col] = o0;
        *(float2*)&g_ao[((size_t)(b * N_ + qlo + 8)) * C_ + col] = o1;
    }
}

// ---------------------------------------------------------------------------
extern "C" void kernel_launch(void* const* d_in, const int* in_sizes, int n_in,
                              void* d_out, int out_size)
{
    (void)in_sizes; (void)n_in; (void)out_size;
    const float* x      = (const float*)d_in[0];
    const float* qkv_w  = (const float*)d_in[1];
    const float* proj_w = (const float*)d_in[2];
    const float* proj_b = (const float*)d_in[3];
    const float* fcos   = (const float*)d_in[4];
    const float* fsin   = (const float*)d_in[5];
    float* out = (float*)d_out;

    // 1) QKV GEMM (tf32) + RoPE scatter
    gemm_tf32_kernel<0><<<dim3(3 * C_ / 128, M_ / 128), 256>>>(
        x, qkv_w, fcos, fsin, nullptr, nullptr);
    // 2) Flash attention (tf32 tensor cores)
    attn_tc_kernel<<<dim3(N_ / 128, B_ * H_), 256>>>();
    // 3) Output projection (tf32) + bias
    gemm_tf32_kernel<1><<<dim3(C_ / 128, M_ / 128), 256>>>(
        nullptr, proj_w, nullptr, nullptr, proj_b, out);
}